// round 1
// baseline (speedup 1.0000x reference)
#include <cuda_runtime.h>
#include <math.h>

#define N_NODES 100000
#define N_EDGES 3200000
#define D 64
#define NEG_SLOPE 0.01f

// ---------------- device scratch (no allocations allowed) ----------------
__device__ float g_s  [N_NODES * D];   // per-layer weighted neighbor sum
__device__ float g_hA [N_NODES * D];   // h1
__device__ float g_hB [N_NODES * D];   // h2
__device__ float g_rsq[N_NODES];       // rsqrt(max(deg,1))
__device__ int   g_deg[N_NODES];
__device__ float g_w  [N_EDGES];       // per-edge norm = rsq[src]*rsq[dst]

// ---------------- small utility kernels ----------------
__global__ void k_zero_deg() {
    int i = blockIdx.x * blockDim.x + threadIdx.x;
    if (i < N_NODES) g_deg[i] = 0;
}

__global__ void k_count(const int* __restrict__ dst) {
    int e = blockIdx.x * blockDim.x + threadIdx.x;
    if (e < N_EDGES) atomicAdd(&g_deg[dst[e]], 1);
}

__global__ void k_rsq() {
    int i = blockIdx.x * blockDim.x + threadIdx.x;
    if (i < N_NODES) {
        int d = g_deg[i];
        g_rsq[i] = rsqrtf((float)(d > 0 ? d : 1));
    }
}

__global__ void k_edge_w(const int* __restrict__ src, const int* __restrict__ dst) {
    int e = blockIdx.x * blockDim.x + threadIdx.x;
    if (e < N_EDGES) g_w[e] = g_rsq[src[e]] * g_rsq[dst[e]];
}

__global__ void k_zero_s() {
    int i = blockIdx.x * blockDim.x + threadIdx.x;  // float4 granularity
    if (i < N_NODES * D / 4) ((float4*)g_s)[i] = make_float4(0.f, 0.f, 0.f, 0.f);
}

// ---------------- edge scatter: s[dst] += w_e * h[src] ----------------
// 16 threads per edge, one float4 chunk each. Gathers hit L2 (25.6MB table).
__global__ void k_scatter(const float* __restrict__ h,
                          const int* __restrict__ src,
                          const int* __restrict__ dst) {
    long long t = (long long)blockIdx.x * blockDim.x + threadIdx.x;
    int e = (int)(t >> 4);
    int c = (int)(t & 15);
    if (e >= N_EDGES) return;
    int sj = src[e];
    int di = dst[e];
    float w = g_w[e];
    float4 v = ((const float4*)(h + (size_t)sj * D))[c];
    v.x *= w; v.y *= w; v.z *= w; v.w *= w;
    float* p = g_s + (size_t)di * D + c * 4;
    asm volatile("red.global.add.v4.f32 [%0], {%1,%2,%3,%4};"
                 :: "l"(p), "f"(v.x), "f"(v.y), "f"(v.z), "f"(v.w)
                 : "memory");
}

// ---------------- combine: out = (h+s)@W1 + (s*h)@W2 (+leaky relu) -------
// One thread per node. W1/W2 staged in shared (broadcast reads), acc[64] in
// registers. FFMA-bound: 8192 FMA/node.
__global__ void __launch_bounds__(128) k_combine(
    const float* __restrict__ hin,
    const float* __restrict__ W1,
    const float* __restrict__ W2,
    float* __restrict__ out,       // [N, 192], write at column colOff
    float* __restrict__ hout,      // next-layer h buffer, may be null
    int do_relu, int colOff)
{
    __shared__ float sW1[D * D];
    __shared__ float sW2[D * D];
    for (int i = threadIdx.x; i < D * D; i += blockDim.x) {
        sW1[i] = W1[i];
        sW2[i] = W2[i];
    }
    __syncthreads();

    int n = blockIdx.x * blockDim.x + threadIdx.x;
    if (n >= N_NODES) return;

    float acc[D];
#pragma unroll
    for (int d = 0; d < D; d++) acc[d] = 0.f;

    const float* xr = hin + (size_t)n * D;
    const float* sr = g_s + (size_t)n * D;

#pragma unroll 2
    for (int k = 0; k < D; k++) {
        float xk = __ldg(xr + k);
        float sk = sr[k];
        float a = xk + sk;      // multiplies W1
        float b = xk * sk;      // multiplies W2
        const float4* w1r = (const float4*)(sW1 + k * D);
        const float4* w2r = (const float4*)(sW2 + k * D);
#pragma unroll
        for (int d4 = 0; d4 < D / 4; d4++) {
            float4 w1 = w1r[d4];
            float4 w2 = w2r[d4];
            acc[4 * d4 + 0] += a * w1.x + b * w2.x;
            acc[4 * d4 + 1] += a * w1.y + b * w2.y;
            acc[4 * d4 + 2] += a * w1.z + b * w2.z;
            acc[4 * d4 + 3] += a * w1.w + b * w2.w;
        }
    }

    float* op = out + (size_t)n * 192 + colOff;
#pragma unroll
    for (int d4 = 0; d4 < D / 4; d4++) {
        float4 v = make_float4(acc[4 * d4 + 0], acc[4 * d4 + 1],
                               acc[4 * d4 + 2], acc[4 * d4 + 3]);
        if (do_relu) {
            v.x = v.x > 0.f ? v.x : NEG_SLOPE * v.x;
            v.y = v.y > 0.f ? v.y : NEG_SLOPE * v.y;
            v.z = v.z > 0.f ? v.z : NEG_SLOPE * v.z;
            v.w = v.w > 0.f ? v.w : NEG_SLOPE * v.w;
        }
        ((float4*)op)[d4] = v;
        if (hout) ((float4*)(hout + (size_t)n * D))[d4] = v;
    }
}

// ---------------- launch ----------------
extern "C" void kernel_launch(void* const* d_in, const int* in_sizes, int n_in,
                              void* d_out, int out_size) {
    const float* x   = (const float*)d_in[0];
    const float* W1a = (const float*)d_in[1];
    const float* W2a = (const float*)d_in[2];
    const float* W1b = (const float*)d_in[3];
    const float* W2b = (const float*)d_in[4];
    const int*   src = (const int*)d_in[5];
    const int*   dst = (const int*)d_in[6];
    float* out = (float*)d_out;

    float* hA; cudaGetSymbolAddress((void**)&hA, g_hA);
    float* hB; cudaGetSymbolAddress((void**)&hB, g_hB);

    const int TB = 256;
    int gN  = (N_NODES + TB - 1) / TB;
    int gE  = (N_EDGES + TB - 1) / TB;
    int gS  = (int)(((long long)N_EDGES * 16 + TB - 1) / TB);
    int gZ  = (N_NODES * D / 4 + TB - 1) / TB;
    int gC  = (N_NODES + 127) / 128;

    // degree + norm precompute
    k_zero_deg<<<gN, TB>>>();
    k_count<<<gE, TB>>>(dst);
    k_rsq<<<gN, TB>>>();
    k_edge_w<<<gE, TB>>>(src, dst);

    // layer 1: h1 = lrelu((x+s)@W1a + (s*x)@W2a)
    k_zero_s<<<gZ, TB>>>();
    k_scatter<<<gS, TB>>>(x, src, dst);
    k_combine<<<gC, 128>>>(x, W1a, W2a, out, hA, 1, 0);

    // layer 2: h2 = lrelu((h1+s)@W1b + (s*h1)@W2b)
    k_zero_s<<<gZ, TB>>>();
    k_scatter<<<gS, TB>>>(hA, src, dst);
    k_combine<<<gC, 128>>>(hA, W1b, W2b, out, hB, 1, 64);

    // layer 3: h3 = (h2+s)@W1b + (s*h2)@W2b   (no activation)
    k_zero_s<<<gZ, TB>>>();
    k_scatter<<<gS, TB>>>(hB, src, dst);
    k_combine<<<gC, 128>>>(hB, W1b, W2b, out, nullptr, 0, 128);
}

// round 2
// speedup vs baseline: 1.4982x; 1.4982x over previous
#include <cuda_runtime.h>
#include <math.h>

#define N_NODES 100000
#define N_EDGES 3200000
#define D 64
#define NEG_SLOPE 0.01f
#define NB_SCAN ((N_NODES + 255) / 256)   // 391

// ---------------- device scratch (no allocations allowed) ----------------
__device__ float g_s  [N_NODES * D];   // per-layer weighted neighbor sum
__device__ float g_hA [N_NODES * D];   // h1
__device__ float g_hB [N_NODES * D];   // h2
__device__ float g_rsq[N_NODES];       // rsqrt(max(deg,1))
__device__ int   g_deg[N_NODES];
__device__ int   g_off[N_NODES + 1];   // CSR row offsets (by dst)
__device__ int   g_cur[N_NODES];       // fill cursors
__device__ int   g_bsum[NB_SCAN];      // scan block sums
__device__ int2  g_edge[N_EDGES];      // {src, bitcast(w)} sorted by dst

// ---------------- degree / norm ----------------
__global__ void k_zero_deg() {
    int i = blockIdx.x * blockDim.x + threadIdx.x;
    if (i < N_NODES) g_deg[i] = 0;
}

__global__ void k_count(const int* __restrict__ dst) {
    int e = blockIdx.x * blockDim.x + threadIdx.x;
    if (e < N_EDGES) atomicAdd(&g_deg[dst[e]], 1);
}

__global__ void k_rsq() {
    int i = blockIdx.x * blockDim.x + threadIdx.x;
    if (i < N_NODES) {
        int d = g_deg[i];
        g_rsq[i] = rsqrtf((float)(d > 0 ? d : 1));
    }
}

// ---------------- CSR build: scan + fill ----------------
__global__ void k_scan_block() {
    __shared__ int sh[256];
    int tid = threadIdx.x;
    int i = blockIdx.x * 256 + tid;
    int v = (i < N_NODES) ? g_deg[i] : 0;
    int val = v;
    sh[tid] = val;
    __syncthreads();
    for (int ofs = 1; ofs < 256; ofs <<= 1) {
        int t = (tid >= ofs) ? sh[tid - ofs] : 0;
        __syncthreads();
        val += t;
        sh[tid] = val;
        __syncthreads();
    }
    if (i < N_NODES) g_off[i] = val - v;          // exclusive within block
    if (tid == 255) g_bsum[blockIdx.x] = val;     // block total
}

__global__ void k_scan_bsum() {                    // 1 block, 512 threads
    __shared__ int sh[512];
    int tid = threadIdx.x;
    int v = (tid < NB_SCAN) ? g_bsum[tid] : 0;
    int val = v;
    sh[tid] = val;
    __syncthreads();
    for (int ofs = 1; ofs < 512; ofs <<= 1) {
        int t = (tid >= ofs) ? sh[tid - ofs] : 0;
        __syncthreads();
        val += t;
        sh[tid] = val;
        __syncthreads();
    }
    if (tid < NB_SCAN) g_bsum[tid] = val - v;     // exclusive across blocks
}

__global__ void k_scan_finish() {
    int i = blockIdx.x * blockDim.x + threadIdx.x;
    if (i < N_NODES) {
        int o = g_off[i] + g_bsum[i >> 8];
        g_off[i] = o;
        g_cur[i] = o;
        if (i == 0) g_off[N_NODES] = N_EDGES;
    }
}

__global__ void k_fill(const int* __restrict__ src, const int* __restrict__ dst) {
    int e = blockIdx.x * blockDim.x + threadIdx.x;
    if (e < N_EDGES) {
        int d = dst[e];
        int s = src[e];
        float w = g_rsq[s] * g_rsq[d];
        int pos = atomicAdd(&g_cur[d], 1);
        g_edge[pos] = make_int2(s, __float_as_int(w));
    }
}

// ---------------- CSR gather: s[i] = sum_e w_e * h[src_e] ----------------
// 16 threads per node, one float4 column chunk each. No atomics, no zeroing.
__global__ void __launch_bounds__(256) k_gather(const float* __restrict__ h) {
    long long t = (long long)blockIdx.x * blockDim.x + threadIdx.x;
    int node = (int)(t >> 4);
    int c = (int)(t & 15);
    if (node >= N_NODES) return;
    int e = g_off[node];
    int end = g_off[node + 1];
    const float4* h4 = (const float4*)h;
    float4 acc = make_float4(0.f, 0.f, 0.f, 0.f);
    // 2-way unroll for MLP
    for (; e + 1 < end; e += 2) {
        int2 e0 = g_edge[e];
        int2 e1 = g_edge[e + 1];
        float w0 = __int_as_float(e0.y);
        float w1 = __int_as_float(e1.y);
        float4 v0 = h4[(size_t)e0.x * 16 + c];
        float4 v1 = h4[(size_t)e1.x * 16 + c];
        acc.x += w0 * v0.x; acc.y += w0 * v0.y;
        acc.z += w0 * v0.z; acc.w += w0 * v0.w;
        acc.x += w1 * v1.x; acc.y += w1 * v1.y;
        acc.z += w1 * v1.z; acc.w += w1 * v1.w;
    }
    if (e < end) {
        int2 e0 = g_edge[e];
        float w0 = __int_as_float(e0.y);
        float4 v0 = h4[(size_t)e0.x * 16 + c];
        acc.x += w0 * v0.x; acc.y += w0 * v0.y;
        acc.z += w0 * v0.z; acc.w += w0 * v0.w;
    }
    ((float4*)g_s)[(size_t)node * 16 + c] = acc;
}

// ---------------- combine: out = (h+s)@W1 + (s*h)@W2 (+leaky relu) -------
__global__ void __launch_bounds__(128) k_combine(
    const float* __restrict__ hin,
    const float* __restrict__ W1,
    const float* __restrict__ W2,
    float* __restrict__ out,       // [N, 192], write at column colOff
    float* __restrict__ hout,      // next-layer h buffer, may be null
    int do_relu, int colOff)
{
    __shared__ float sW1[D * D];
    __shared__ float sW2[D * D];
    for (int i = threadIdx.x; i < D * D; i += blockDim.x) {
        sW1[i] = W1[i];
        sW2[i] = W2[i];
    }
    __syncthreads();

    int n = blockIdx.x * blockDim.x + threadIdx.x;
    if (n >= N_NODES) return;

    float acc[D];
#pragma unroll
    for (int d = 0; d < D; d++) acc[d] = 0.f;

    const float* xr = hin + (size_t)n * D;
    const float* sr = g_s + (size_t)n * D;

#pragma unroll 2
    for (int k = 0; k < D; k++) {
        float xk = __ldg(xr + k);
        float sk = sr[k];
        float a = xk + sk;      // multiplies W1
        float b = xk * sk;      // multiplies W2
        const float4* w1r = (const float4*)(sW1 + k * D);
        const float4* w2r = (const float4*)(sW2 + k * D);
#pragma unroll
        for (int d4 = 0; d4 < D / 4; d4++) {
            float4 w1 = w1r[d4];
            float4 w2 = w2r[d4];
            acc[4 * d4 + 0] += a * w1.x + b * w2.x;
            acc[4 * d4 + 1] += a * w1.y + b * w2.y;
            acc[4 * d4 + 2] += a * w1.z + b * w2.z;
            acc[4 * d4 + 3] += a * w1.w + b * w2.w;
        }
    }

    float* op = out + (size_t)n * 192 + colOff;
#pragma unroll
    for (int d4 = 0; d4 < D / 4; d4++) {
        float4 v = make_float4(acc[4 * d4 + 0], acc[4 * d4 + 1],
                               acc[4 * d4 + 2], acc[4 * d4 + 3]);
        if (do_relu) {
            v.x = v.x > 0.f ? v.x : NEG_SLOPE * v.x;
            v.y = v.y > 0.f ? v.y : NEG_SLOPE * v.y;
            v.z = v.z > 0.f ? v.z : NEG_SLOPE * v.z;
            v.w = v.w > 0.f ? v.w : NEG_SLOPE * v.w;
        }
        ((float4*)op)[d4] = v;
        if (hout) ((float4*)(hout + (size_t)n * D))[d4] = v;
    }
}

// ---------------- launch ----------------
extern "C" void kernel_launch(void* const* d_in, const int* in_sizes, int n_in,
                              void* d_out, int out_size) {
    const float* x   = (const float*)d_in[0];
    const float* W1a = (const float*)d_in[1];
    const float* W2a = (const float*)d_in[2];
    const float* W1b = (const float*)d_in[3];
    const float* W2b = (const float*)d_in[4];
    const int*   src = (const int*)d_in[5];
    const int*   dst = (const int*)d_in[6];
    float* out = (float*)d_out;

    float* hA; cudaGetSymbolAddress((void**)&hA, g_hA);
    float* hB; cudaGetSymbolAddress((void**)&hB, g_hB);

    const int TB = 256;
    int gN = (N_NODES + TB - 1) / TB;
    int gE = (N_EDGES + TB - 1) / TB;
    int gG = (int)(((long long)N_NODES * 16 + TB - 1) / TB);
    int gC = (N_NODES + 127) / 128;

    // degree + norm + CSR build (by dst)
    k_zero_deg<<<gN, TB>>>();
    k_count<<<gE, TB>>>(dst);
    k_rsq<<<gN, TB>>>();
    k_scan_block<<<NB_SCAN, 256>>>();
    k_scan_bsum<<<1, 512>>>();
    k_scan_finish<<<gN, TB>>>();
    k_fill<<<gE, TB>>>(src, dst);

    // layer 1: h1 = lrelu((x+s)@W1a + (s*x)@W2a)
    k_gather<<<gG, TB>>>(x);
    k_combine<<<gC, 128>>>(x, W1a, W2a, out, hA, 1, 0);

    // layer 2: h2 = lrelu((h1+s)@W1b + (s*h1)@W2b)
    k_gather<<<gG, TB>>>(hA);
    k_combine<<<gC, 128>>>(hA, W1b, W2b, out, hB, 1, 64);

    // layer 3: h3 = (h2+s)@W1b + (s*h2)@W2b   (no activation)
    k_gather<<<gG, TB>>>(hB);
    k_combine<<<gC, 128>>>(hB, W1b, W2b, out, nullptr, 0, 128);
}

// round 3
// speedup vs baseline: 1.6417x; 1.0958x over previous
#include <cuda_runtime.h>
#include <cuda_fp16.h>
#include <math.h>

#define N_NODES 100000
#define N_EDGES 3200000
#define D 64
#define NEG_SLOPE 0.01f
#define NB_SCAN ((N_NODES + 255) / 256)   // 391

// ---------------- device scratch (no allocations allowed) ----------------
__device__ float  g_s  [N_NODES * D];   // per-layer weighted neighbor sum (fp32)
__device__ float  g_hA [N_NODES * D];   // h1 fp32
__device__ float  g_hB [N_NODES * D];   // h2 fp32
__device__ __half g_xh [N_NODES * D];   // fp16 copies for gather
__device__ __half g_hAh[N_NODES * D];
__device__ __half g_hBh[N_NODES * D];
__device__ float  g_rsq[N_NODES];
__device__ int    g_deg[N_NODES];
__device__ int    g_off[N_NODES + 1];
__device__ int    g_cur[N_NODES];
__device__ int    g_bsum[NB_SCAN];
__device__ int2   g_edge[N_EDGES];      // {src, bitcast(w)} sorted by dst

// ---------------- f32x2 helpers ----------------
__device__ __forceinline__ void ffma2(unsigned long long& d,
                                      unsigned long long a,
                                      unsigned long long b) {
    asm("fma.rn.f32x2 %0, %1, %2, %0;" : "+l"(d) : "l"(a), "l"(b));
}
__device__ __forceinline__ unsigned long long pack2(float v) {
    unsigned long long r;
    asm("mov.b64 %0, {%1, %1};" : "=l"(r) : "f"(v));
    return r;
}
__device__ __forceinline__ float2 unpack2(unsigned long long v) {
    float2 r;
    asm("mov.b64 {%0, %1}, %2;" : "=f"(r.x), "=f"(r.y) : "l"(v));
    return r;
}

// ---------------- degree / norm ----------------
__global__ void k_zero_deg() {
    int i = blockIdx.x * blockDim.x + threadIdx.x;
    if (i < N_NODES) g_deg[i] = 0;
}
__global__ void k_count(const int* __restrict__ dst) {
    int e = blockIdx.x * blockDim.x + threadIdx.x;
    if (e < N_EDGES) atomicAdd(&g_deg[dst[e]], 1);
}
__global__ void k_rsq() {
    int i = blockIdx.x * blockDim.x + threadIdx.x;
    if (i < N_NODES) {
        int d = g_deg[i];
        g_rsq[i] = rsqrtf((float)(d > 0 ? d : 1));
    }
}

// ---------------- CSR build: scan + fill ----------------
__global__ void k_scan_block() {
    __shared__ int sh[256];
    int tid = threadIdx.x;
    int i = blockIdx.x * 256 + tid;
    int v = (i < N_NODES) ? g_deg[i] : 0;
    int val = v;
    sh[tid] = val;
    __syncthreads();
    for (int ofs = 1; ofs < 256; ofs <<= 1) {
        int t = (tid >= ofs) ? sh[tid - ofs] : 0;
        __syncthreads();
        val += t;
        sh[tid] = val;
        __syncthreads();
    }
    if (i < N_NODES) g_off[i] = val - v;
    if (tid == 255) g_bsum[blockIdx.x] = val;
}
__global__ void k_scan_bsum() {
    __shared__ int sh[512];
    int tid = threadIdx.x;
    int v = (tid < NB_SCAN) ? g_bsum[tid] : 0;
    int val = v;
    sh[tid] = val;
    __syncthreads();
    for (int ofs = 1; ofs < 512; ofs <<= 1) {
        int t = (tid >= ofs) ? sh[tid - ofs] : 0;
        __syncthreads();
        val += t;
        sh[tid] = val;
        __syncthreads();
    }
    if (tid < NB_SCAN) g_bsum[tid] = val - v;
}
__global__ void k_scan_finish() {
    int i = blockIdx.x * blockDim.x + threadIdx.x;
    if (i < N_NODES) {
        int o = g_off[i] + g_bsum[i >> 8];
        g_off[i] = o;
        g_cur[i] = o;
        if (i == 0) g_off[N_NODES] = N_EDGES;
    }
}
__global__ void k_fill(const int* __restrict__ src, const int* __restrict__ dst) {
    int e = blockIdx.x * blockDim.x + threadIdx.x;
    if (e < N_EDGES) {
        int d = dst[e];
        int s = src[e];
        float w = g_rsq[s] * g_rsq[d];
        int pos = atomicAdd(&g_cur[d], 1);
        g_edge[pos] = make_int2(s, __float_as_int(w));
    }
}

// ---------------- fp32 -> fp16 convert (for x only) ----------------
__global__ void k_tohalf(const float* __restrict__ src) {
    int i = blockIdx.x * blockDim.x + threadIdx.x;   // float4 granularity
    if (i < N_NODES * D / 4) {
        float4 v = ((const float4*)src)[i];
        half2 a = __floats2half2_rn(v.x, v.y);
        half2 b = __floats2half2_rn(v.z, v.w);
        uint2 o;
        o.x = *(unsigned int*)&a;
        o.y = *(unsigned int*)&b;
        ((uint2*)g_xh)[i] = o;
    }
}

// ---------------- CSR gather: s[i] = sum_e w_e * h16[src_e] ----------------
// 8 threads per node, 8 fp16 columns (one uint4) each. fp32 accumulate.
__device__ __forceinline__ void acc8(float acc[8], uint4 v, float w) {
    float2 f0 = __half22float2(*(half2*)&v.x);
    float2 f1 = __half22float2(*(half2*)&v.y);
    float2 f2 = __half22float2(*(half2*)&v.z);
    float2 f3 = __half22float2(*(half2*)&v.w);
    acc[0] += w * f0.x; acc[1] += w * f0.y;
    acc[2] += w * f1.x; acc[3] += w * f1.y;
    acc[4] += w * f2.x; acc[5] += w * f2.y;
    acc[6] += w * f3.x; acc[7] += w * f3.y;
}

__global__ void __launch_bounds__(256) k_gather(const __half* __restrict__ h) {
    long long t = (long long)blockIdx.x * blockDim.x + threadIdx.x;
    int node = (int)(t >> 3);
    int c = (int)(t & 7);          // cols c*8 .. c*8+7
    if (node >= N_NODES) return;
    int e = g_off[node];
    int end = g_off[node + 1];
    const uint4* h4 = (const uint4*)h;   // 8 halves per uint4; 8 per row
    float acc[8];
#pragma unroll
    for (int j = 0; j < 8; j++) acc[j] = 0.f;

    for (; e + 3 < end; e += 4) {
        int2 E0 = g_edge[e];
        int2 E1 = g_edge[e + 1];
        int2 E2 = g_edge[e + 2];
        int2 E3 = g_edge[e + 3];
        uint4 v0 = h4[(size_t)E0.x * 8 + c];
        uint4 v1 = h4[(size_t)E1.x * 8 + c];
        uint4 v2 = h4[(size_t)E2.x * 8 + c];
        uint4 v3 = h4[(size_t)E3.x * 8 + c];
        acc8(acc, v0, __int_as_float(E0.y));
        acc8(acc, v1, __int_as_float(E1.y));
        acc8(acc, v2, __int_as_float(E2.y));
        acc8(acc, v3, __int_as_float(E3.y));
    }
    for (; e < end; e++) {
        int2 E0 = g_edge[e];
        uint4 v0 = h4[(size_t)E0.x * 8 + c];
        acc8(acc, v0, __int_as_float(E0.y));
    }
    float4* so = (float4*)(g_s + (size_t)node * D + c * 8);
    so[0] = make_float4(acc[0], acc[1], acc[2], acc[3]);
    so[1] = make_float4(acc[4], acc[5], acc[6], acc[7]);
}

// ---------------- combine: out = (h+s)@W1 + (s*h)@W2 (+leaky relu) -------
// 1 thread/node, f32x2 accumulators (32 packed pairs), W in shared.
__global__ void __launch_bounds__(128) k_combine(
    const float* __restrict__ hin,
    const float* __restrict__ W1,
    const float* __restrict__ W2,
    float* __restrict__ out,       // [N, 192] at colOff
    float* __restrict__ houtF,     // next-layer fp32 h, may be null
    __half* __restrict__ houtH,    // next-layer fp16 h, may be null
    int do_relu, int colOff)
{
    __shared__ __align__(16) float sW1[D * D];
    __shared__ __align__(16) float sW2[D * D];
    {
        const float4* w1 = (const float4*)W1;
        const float4* w2 = (const float4*)W2;
        float4* d1 = (float4*)sW1;
        float4* d2 = (float4*)sW2;
        for (int i = threadIdx.x; i < D * D / 4; i += blockDim.x) {
            d1[i] = w1[i];
            d2[i] = w2[i];
        }
    }
    __syncthreads();

    int n = blockIdx.x * blockDim.x + threadIdx.x;
    if (n >= N_NODES) return;

    unsigned long long acc[D / 2];
#pragma unroll
    for (int j = 0; j < D / 2; j++) acc[j] = 0ULL;

    const float* xr = hin + (size_t)n * D;
    const float* sr = g_s + (size_t)n * D;

#pragma unroll 2
    for (int k = 0; k < D; k++) {
        float xk = __ldg(xr + k);
        float sk = sr[k];
        unsigned long long a2 = pack2(xk + sk);   // * W1
        unsigned long long b2 = pack2(xk * sk);   // * W2
        const double2* w1r = (const double2*)(sW1 + k * D);
        const double2* w2r = (const double2*)(sW2 + k * D);
#pragma unroll
        for (int j = 0; j < D / 4; j++) {         // 16 double2 per matrix row
            double2 w1 = w1r[j];
            double2 w2 = w2r[j];
            ffma2(acc[2 * j + 0], a2, __double_as_longlong(w1.x));
            ffma2(acc[2 * j + 1], a2, __double_as_longlong(w1.y));
            ffma2(acc[2 * j + 0], b2, __double_as_longlong(w2.x));
            ffma2(acc[2 * j + 1], b2, __double_as_longlong(w2.y));
        }
    }

    float* op = out + (size_t)n * 192 + colOff;
    float* hf = houtF ? houtF + (size_t)n * D : nullptr;
    __half* hh = houtH ? houtH + (size_t)n * D : nullptr;

#pragma unroll
    for (int j = 0; j < D / 4; j++) {
        float2 p0 = unpack2(acc[2 * j + 0]);
        float2 p1 = unpack2(acc[2 * j + 1]);
        float4 v = make_float4(p0.x, p0.y, p1.x, p1.y);
        if (do_relu) {
            v.x = v.x > 0.f ? v.x : NEG_SLOPE * v.x;
            v.y = v.y > 0.f ? v.y : NEG_SLOPE * v.y;
            v.z = v.z > 0.f ? v.z : NEG_SLOPE * v.z;
            v.w = v.w > 0.f ? v.w : NEG_SLOPE * v.w;
        }
        ((float4*)op)[j] = v;
        if (hf) ((float4*)hf)[j] = v;
        if (hh) {
            half2 a = __floats2half2_rn(v.x, v.y);
            half2 b = __floats2half2_rn(v.z, v.w);
            uint2 o;
            o.x = *(unsigned int*)&a;
            o.y = *(unsigned int*)&b;
            ((uint2*)hh)[j] = o;
        }
    }
}

// ---------------- launch ----------------
extern "C" void kernel_launch(void* const* d_in, const int* in_sizes, int n_in,
                              void* d_out, int out_size) {
    const float* x   = (const float*)d_in[0];
    const float* W1a = (const float*)d_in[1];
    const float* W2a = (const float*)d_in[2];
    const float* W1b = (const float*)d_in[3];
    const float* W2b = (const float*)d_in[4];
    const int*   src = (const int*)d_in[5];
    const int*   dst = (const int*)d_in[6];
    float* out = (float*)d_out;

    float*  hA;  cudaGetSymbolAddress((void**)&hA,  g_hA);
    float*  hB;  cudaGetSymbolAddress((void**)&hB,  g_hB);
    __half* xh;  cudaGetSymbolAddress((void**)&xh,  g_xh);
    __half* hAh; cudaGetSymbolAddress((void**)&hAh, g_hAh);
    __half* hBh; cudaGetSymbolAddress((void**)&hBh, g_hBh);

    const int TB = 256;
    int gN = (N_NODES + TB - 1) / TB;
    int gE = (N_EDGES + TB - 1) / TB;
    int gG = (int)(((long long)N_NODES * 8 + TB - 1) / TB);
    int gH = (N_NODES * D / 4 + TB - 1) / TB;
    int gC = (N_NODES + 127) / 128;

    // degree + norm + CSR build (by dst)
    k_zero_deg<<<gN, TB>>>();
    k_count<<<gE, TB>>>(dst);
    k_rsq<<<gN, TB>>>();
    k_scan_block<<<NB_SCAN, 256>>>();
    k_scan_bsum<<<1, 512>>>();
    k_scan_finish<<<gN, TB>>>();
    k_fill<<<gE, TB>>>(src, dst);
    k_tohalf<<<gH, TB>>>(x);

    // layer 1
    k_gather<<<gG, TB>>>(xh);
    k_combine<<<gC, 128>>>(x, W1a, W2a, out, hA, hAh, 1, 0);

    // layer 2
    k_gather<<<gG, TB>>>(hAh);
    k_combine<<<gC, 128>>>(hA, W1b, W2b, out, hB, hBh, 1, 64);

    // layer 3 (no activation)
    k_gather<<<gG, TB>>>(hBh);
    k_combine<<<gC, 128>>>(hB, W1b, W2b, out, nullptr, nullptr, 0, 128);
}

// round 4
// speedup vs baseline: 1.7809x; 1.0848x over previous
#include <cuda_runtime.h>
#include <cuda_fp16.h>
#include <math.h>

#define N_NODES 100000
#define N_EDGES 3200000
#define D 64
#define NEG_SLOPE 0.01f
#define NB_SCAN ((N_NODES + 255) / 256)   // 391

#define NPB 64          // nodes per fused block
#define TPB 512         // 8 threads per node
#define AB_STRIDE 68    // floats; multiple of 4 (alignment), %32==4 (bank skew)
// dynamic smem: W1 4096 + W2 4096 + sa 64*68 + sb 64*68 floats
#define SMEM_FLOATS (4096 + 4096 + NPB * AB_STRIDE * 2)
#define SMEM_BYTES (SMEM_FLOATS * 4)

// ---------------- device scratch (no allocations allowed) ----------------
__device__ float  g_hA [N_NODES * D];   // h1 fp32
__device__ float  g_hB [N_NODES * D];   // h2 fp32
__device__ __half g_xh [N_NODES * D];   // fp16 copies for gather
__device__ __half g_hAh[N_NODES * D];
__device__ __half g_hBh[N_NODES * D];
__device__ float  g_rsq[N_NODES];
__device__ int    g_deg[N_NODES];
__device__ int    g_off[N_NODES + 1];
__device__ int    g_cur[N_NODES];
__device__ int    g_bsum[NB_SCAN];
__device__ int2   g_edge[N_EDGES];      // {src, bitcast(w)} sorted by dst

// ---------------- f32x2 helpers ----------------
__device__ __forceinline__ void ffma2(unsigned long long& d,
                                      unsigned long long a,
                                      unsigned long long b) {
    asm("fma.rn.f32x2 %0, %1, %2, %0;" : "+l"(d) : "l"(a), "l"(b));
}
__device__ __forceinline__ unsigned long long pack2(float v) {
    unsigned long long r;
    asm("mov.b64 %0, {%1, %1};" : "=l"(r) : "f"(v));
    return r;
}
__device__ __forceinline__ float2 unpack2(unsigned long long v) {
    float2 r;
    asm("mov.b64 {%0, %1}, %2;" : "=f"(r.x), "=f"(r.y) : "l"(v));
    return r;
}

// ---------------- degree / norm / CSR build ----------------
__global__ void k_zero_deg() {
    int i = blockIdx.x * blockDim.x + threadIdx.x;
    if (i < N_NODES) g_deg[i] = 0;
}
__global__ void k_count(const int* __restrict__ dst) {
    int e = blockIdx.x * blockDim.x + threadIdx.x;
    if (e < N_EDGES) atomicAdd(&g_deg[dst[e]], 1);
}
__global__ void k_scan_block() {
    __shared__ int sh[256];
    int tid = threadIdx.x;
    int i = blockIdx.x * 256 + tid;
    int v = (i < N_NODES) ? g_deg[i] : 0;
    int val = v;
    sh[tid] = val;
    __syncthreads();
    for (int ofs = 1; ofs < 256; ofs <<= 1) {
        int t = (tid >= ofs) ? sh[tid - ofs] : 0;
        __syncthreads();
        val += t;
        sh[tid] = val;
        __syncthreads();
    }
    if (i < N_NODES) g_off[i] = val - v;
    if (tid == 255) g_bsum[blockIdx.x] = val;
}
__global__ void k_scan_bsum() {
    __shared__ int sh[512];
    int tid = threadIdx.x;
    int v = (tid < NB_SCAN) ? g_bsum[tid] : 0;
    int val = v;
    sh[tid] = val;
    __syncthreads();
    for (int ofs = 1; ofs < 512; ofs <<= 1) {
        int t = (tid >= ofs) ? sh[tid - ofs] : 0;
        __syncthreads();
        val += t;
        sh[tid] = val;
        __syncthreads();
    }
    if (tid < NB_SCAN) g_bsum[tid] = val - v;
}
__global__ void k_scan_finish() {   // offsets + cursors + rsq in one pass
    int i = blockIdx.x * blockDim.x + threadIdx.x;
    if (i < N_NODES) {
        int o = g_off[i] + g_bsum[i >> 8];
        g_off[i] = o;
        g_cur[i] = o;
        int d = g_deg[i];
        g_rsq[i] = rsqrtf((float)(d > 0 ? d : 1));
        if (i == 0) g_off[N_NODES] = N_EDGES;
    }
}
__global__ void k_fill(const int* __restrict__ src, const int* __restrict__ dst) {
    int e = blockIdx.x * blockDim.x + threadIdx.x;
    if (e < N_EDGES) {
        int d = dst[e];
        int s = src[e];
        float w = g_rsq[s] * g_rsq[d];
        int pos = atomicAdd(&g_cur[d], 1);
        g_edge[pos] = make_int2(s, __float_as_int(w));
    }
}
__global__ void k_tohalf(const float* __restrict__ src) {
    int i = blockIdx.x * blockDim.x + threadIdx.x;   // float4 granularity
    if (i < N_NODES * D / 4) {
        float4 v = ((const float4*)src)[i];
        half2 a = __floats2half2_rn(v.x, v.y);
        half2 b = __floats2half2_rn(v.z, v.w);
        uint2 o;
        o.x = *(unsigned int*)&a;
        o.y = *(unsigned int*)&b;
        ((uint2*)g_xh)[i] = o;
    }
}

// ---------------- fused layer: gather + combine ----------------
// block = 64 nodes * 8 threads. Thread (nl, c) owns output cols c*8..c*8+7.
__device__ __forceinline__ void acc8h(float acc[8], uint4 v, float w) {
    float2 f0 = __half22float2(*(half2*)&v.x);
    float2 f1 = __half22float2(*(half2*)&v.y);
    float2 f2 = __half22float2(*(half2*)&v.z);
    float2 f3 = __half22float2(*(half2*)&v.w);
    acc[0] += w * f0.x; acc[1] += w * f0.y;
    acc[2] += w * f1.x; acc[3] += w * f1.y;
    acc[4] += w * f2.x; acc[5] += w * f2.y;
    acc[6] += w * f3.x; acc[7] += w * f3.y;
}

__global__ void __launch_bounds__(TPB) k_fused(
    const __half* __restrict__ hh,    // fp16 rows for gather
    const float* __restrict__ hin,    // fp32 rows for self/product term
    const float* __restrict__ W1,
    const float* __restrict__ W2,
    float* __restrict__ out,          // [N,192] at colOff
    float* __restrict__ houtF,        // may be null
    __half* __restrict__ houtH,       // may be null
    int do_relu, int colOff)
{
    extern __shared__ __align__(16) float smem[];
    float* sW1 = smem;                 // [64*64] permuted
    float* sW2 = smem + 4096;          // [64*64] permuted
    float* sa  = smem + 8192;          // [NPB][AB_STRIDE]
    float* sb  = sa + NPB * AB_STRIDE;

    // Load weights with permutation so that for each row k, the 8 per-thread
    // double2 chunks of each half-row sit inside one 128B window:
    // col d -> offset (k<<6) | (((d>>2)&1)<<5) | ((d>>3)<<2) | (d&3)
    for (int i = threadIdx.x; i < 4096; i += TPB) {
        int k = i >> 6, d = i & 63;
        int perm = (k << 6) | (((d >> 2) & 1) << 5) | ((d >> 3) << 2) | (d & 3);
        sW1[perm] = W1[i];
        sW2[perm] = W2[i];
    }

    int nl = threadIdx.x >> 3;         // 0..63
    int c  = threadIdx.x & 7;          // 0..7
    int node = blockIdx.x * NPB + nl;
    bool active = node < N_NODES;

    if (active) {
        // ---- gather: s chunk (8 cols) in registers ----
        float acc[8];
#pragma unroll
        for (int j = 0; j < 8; j++) acc[j] = 0.f;
        int e = g_off[node];
        int end = g_off[node + 1];
        const uint4* h4 = (const uint4*)hh;
        for (; e + 3 < end; e += 4) {
            int2 E0 = g_edge[e];
            int2 E1 = g_edge[e + 1];
            int2 E2 = g_edge[e + 2];
            int2 E3 = g_edge[e + 3];
            uint4 v0 = h4[(size_t)E0.x * 8 + c];
            uint4 v1 = h4[(size_t)E1.x * 8 + c];
            uint4 v2 = h4[(size_t)E2.x * 8 + c];
            uint4 v3 = h4[(size_t)E3.x * 8 + c];
            acc8h(acc, v0, __int_as_float(E0.y));
            acc8h(acc, v1, __int_as_float(E1.y));
            acc8h(acc, v2, __int_as_float(E2.y));
            acc8h(acc, v3, __int_as_float(E3.y));
        }
        for (; e < end; e++) {
            int2 E0 = g_edge[e];
            uint4 v0 = h4[(size_t)E0.x * 8 + c];
            acc8h(acc, v0, __int_as_float(E0.y));
        }

        // ---- a = x + s, b = x * s into shared staging ----
        const float4* xr = (const float4*)(hin + (size_t)node * D + c * 8);
        float4 x0 = xr[0];
        float4 x1 = xr[1];
        float* pa = sa + nl * AB_STRIDE + c * 8;
        float* pb = sb + nl * AB_STRIDE + c * 8;
        ((float4*)pa)[0] = make_float4(x0.x + acc[0], x0.y + acc[1],
                                       x0.z + acc[2], x0.w + acc[3]);
        ((float4*)pa)[1] = make_float4(x1.x + acc[4], x1.y + acc[5],
                                       x1.z + acc[6], x1.w + acc[7]);
        ((float4*)pb)[0] = make_float4(x0.x * acc[0], x0.y * acc[1],
                                       x0.z * acc[2], x0.w * acc[3]);
        ((float4*)pb)[1] = make_float4(x1.x * acc[4], x1.y * acc[5],
                                       x1.z * acc[6], x1.w * acc[7]);
    }
    __syncthreads();

    if (!active) return;

    // ---- matvec: acc2[j] (f32x2) over 64 k steps ----
    unsigned long long acc2[4];
#pragma unroll
    for (int j = 0; j < 4; j++) acc2[j] = 0ULL;

    const float* par = sa + nl * AB_STRIDE;
    const float* pbr = sb + nl * AB_STRIDE;

#pragma unroll 4
    for (int k4 = 0; k4 < 16; k4++) {
        float4 av = ((const float4*)par)[k4];
        float4 bv = ((const float4*)pbr)[k4];
        const float* a_ = (const float*)&av;
        const float* b_ = (const float*)&bv;
#pragma unroll
        for (int kk = 0; kk < 4; kk++) {
            int k = k4 * 4 + kk;
            unsigned long long a2 = pack2(a_[kk]);
            unsigned long long b2 = pack2(b_[kk]);
            const double2* w1r = (const double2*)(sW1 + (k << 6)) + c;
            const double2* w2r = (const double2*)(sW2 + (k << 6)) + c;
            double2 wA = w1r[0];
            double2 wB = w1r[8];
            double2 wC = w2r[0];
            double2 wD = w2r[8];
            ffma2(acc2[0], a2, __double_as_longlong(wA.x));
            ffma2(acc2[1], a2, __double_as_longlong(wA.y));
            ffma2(acc2[2], a2, __double_as_longlong(wB.x));
            ffma2(acc2[3], a2, __double_as_longlong(wB.y));
            ffma2(acc2[0], b2, __double_as_longlong(wC.x));
            ffma2(acc2[1], b2, __double_as_longlong(wC.y));
            ffma2(acc2[2], b2, __double_as_longlong(wD.x));
            ffma2(acc2[3], b2, __double_as_longlong(wD.y));
        }
    }

    // ---- epilogue: leaky relu, write out / houtF / houtH ----
    float2 p0 = unpack2(acc2[0]);
    float2 p1 = unpack2(acc2[1]);
    float2 p2 = unpack2(acc2[2]);
    float2 p3 = unpack2(acc2[3]);
    float v[8] = {p0.x, p0.y, p1.x, p1.y, p2.x, p2.y, p3.x, p3.y};
    if (do_relu) {
#pragma unroll
        for (int j = 0; j < 8; j++) v[j] = v[j] > 0.f ? v[j] : NEG_SLOPE * v[j];
    }
    float4 o0 = make_float4(v[0], v[1], v[2], v[3]);
    float4 o1 = make_float4(v[4], v[5], v[6], v[7]);

    float* op = out + (size_t)node * 192 + colOff + c * 8;
    ((float4*)op)[0] = o0;
    ((float4*)op)[1] = o1;
    if (houtF) {
        float* hf = houtF + (size_t)node * D + c * 8;
        ((float4*)hf)[0] = o0;
        ((float4*)hf)[1] = o1;
    }
    if (houtH) {
        half2 h0 = __floats2half2_rn(v[0], v[1]);
        half2 h1 = __floats2half2_rn(v[2], v[3]);
        half2 h2 = __floats2half2_rn(v[4], v[5]);
        half2 h3 = __floats2half2_rn(v[6], v[7]);
        uint4 ho;
        ho.x = *(unsigned int*)&h0;
        ho.y = *(unsigned int*)&h1;
        ho.z = *(unsigned int*)&h2;
        ho.w = *(unsigned int*)&h3;
        ((uint4*)(houtH + (size_t)node * D))[c] = ho;
    }
}

// ---------------- launch ----------------
extern "C" void kernel_launch(void* const* d_in, const int* in_sizes, int n_in,
                              void* d_out, int out_size) {
    const float* x   = (const float*)d_in[0];
    const float* W1a = (const float*)d_in[1];
    const float* W2a = (const float*)d_in[2];
    const float* W1b = (const float*)d_in[3];
    const float* W2b = (const float*)d_in[4];
    const int*   src = (const int*)d_in[5];
    const int*   dst = (const int*)d_in[6];
    float* out = (float*)d_out;

    float*  hA;  cudaGetSymbolAddress((void**)&hA,  g_hA);
    float*  hB;  cudaGetSymbolAddress((void**)&hB,  g_hB);
    __half* xh;  cudaGetSymbolAddress((void**)&xh,  g_xh);
    __half* hAh; cudaGetSymbolAddress((void**)&hAh, g_hAh);
    __half* hBh; cudaGetSymbolAddress((void**)&hBh, g_hBh);

    cudaFuncSetAttribute(k_fused, cudaFuncAttributeMaxDynamicSharedMemorySize,
                         SMEM_BYTES);

    const int TB = 256;
    int gN = (N_NODES + TB - 1) / TB;
    int gE = (N_EDGES + TB - 1) / TB;
    int gH = (N_NODES * D / 4 + TB - 1) / TB;
    int gF = (N_NODES + NPB - 1) / NPB;

    // degree + CSR build (by dst) + fp16 copy of x
    k_zero_deg<<<gN, TB>>>();
    k_count<<<gE, TB>>>(dst);
    k_scan_block<<<NB_SCAN, 256>>>();
    k_scan_bsum<<<1, 512>>>();
    k_scan_finish<<<gN, TB>>>();
    k_fill<<<gE, TB>>>(src, dst);
    k_tohalf<<<gH, TB>>>(x);

    // layer 1
    k_fused<<<gF, TPB, SMEM_BYTES>>>(xh, x, W1a, W2a, out, hA, hAh, 1, 0);
    // layer 2
    k_fused<<<gF, TPB, SMEM_BYTES>>>(hAh, hA, W1b, W2b, out, hB, hBh, 1, 64);
    // layer 3 (no activation)
    k_fused<<<gF, TPB, SMEM_BYTES>>>(hBh, hB, W1b, W2b, out, nullptr, nullptr, 0, 128);
}